// round 3
// baseline (speedup 1.0000x reference)
#include <cuda_runtime.h>

typedef unsigned long long ull;

#define SEQ 64
#define DM 32
#define DI 64
#define HW 1024

// Packed f32x2 helpers (sm_103a FFMA2 — ptxas never auto-fuses these)
#define FMA2(d, a, b, c) \
    asm("fma.rn.f32x2 %0, %1, %2, %3;" : "=l"(d) : "l"(a), "l"(b), "l"(c))
#define MUL2(d, a, b) \
    asm("mul.rn.f32x2 %0, %1, %2;" : "=l"(d) : "l"(a), "l"(b))
__device__ __forceinline__ ull pack2(float lo, float hi) {
    ull r; asm("mov.b64 %0, {%1, %2};" : "=l"(r) : "f"(lo), "f"(hi)); return r;
}
__device__ __forceinline__ float2 unpack2(ull v) {
    float2 f; asm("mov.b64 {%0, %1}, %2;" : "=f"(f.x), "=f"(f.y) : "l"(v)); return f;
}

// Scratch: x transposed to [BB=2048][S=64][DM=32]
__device__ float g_xr[2 * HW * SEQ * DM];

// ---------------- transpose: x [2][64][32][1024] -> g_xr [bb][t][m] ----------------
__global__ __launch_bounds__(256) void transpose_kernel(const float* __restrict__ x) {
    __shared__ float tile[DM][65];
    const int bi = blockIdx.x;             // 2*64*16 = 2048 blocks
    const int c  = bi & 15;                // 64-wide hw chunk
    const int t  = (bi >> 4) & 63;
    const int b  = bi >> 10;
    const float* src = x + ((b * SEQ + t) * DM) * HW + c * 64;
    const int tid = threadIdx.x;
    #pragma unroll
    for (int i = 0; i < 8; i++) {
        int idx = tid + i * 256;
        int m = idx >> 6, hw = idx & 63;
        tile[m][hw] = src[m * HW + hw];
    }
    __syncthreads();
    #pragma unroll
    for (int i = 0; i < 8; i++) {
        int idx = tid + i * 256;
        int hw = idx >> 5, m = idx & 31;
        g_xr[(b * HW + c * 64 + hw) * (SEQ * DM) + t * DM + m] = tile[m][hw];
    }
}

// ---------------- fused mamba: 1 sequence = 2 warps, named-barrier coupled ----------------
__global__ __launch_bounds__(256, 2) void mamba_main(
    const float* __restrict__ in_proj_w,  // [128,32]
    const float* __restrict__ conv_w,     // [64,1,4]
    const float* __restrict__ conv_b,     // [64]
    const float* __restrict__ x_proj_w,   // [34,64]
    const float* __restrict__ dt_proj_w,  // [64,2]
    const float* __restrict__ dt_proj_b,  // [64]
    const float* __restrict__ A_log,      // [64,16]
    const float* __restrict__ Dp,         // [64]
    const float* __restrict__ out_proj_w, // [32,64]
    const float* __restrict__ lin1_w,     // [16,32]
    const float* __restrict__ lin1_b,     // [16]
    const float* __restrict__ lin2_w,     // [1,16]
    const float* __restrict__ lin2_b,     // [1]
    float* __restrict__ out)              // [2,64,1024]
{
    __shared__ float xpw_s[34][66];       // padded: (row*33 + q8) mod 32 distinct -> conflict-free LDS.64
    __shared__ float xin_s[2][4][DM];     // double-buffered input slab per seq
    __shared__ float xt_s[2][4][DI];      // double-buffered conv output per seq
    __shared__ float dbc_s[4][2][32];     // per-warp private copy: [0:16)=B, [16:32)=C
    __shared__ float part_s[4][SEQ][2];
    __shared__ float wm_s[DM];
    __shared__ float v_sm[DI];
    __shared__ float a_s[DI][18];         // general-A fallback
    __shared__ float c_sm;
    __shared__ int slow_s;

    const int tid = threadIdx.x;
    const int j = tid >> 6;               // sequence in block (0..3)
    const int d = tid & 63;               // channel
    const int w = (tid >> 5) & 1;         // warp within sequence
    const int l = tid & 31;               // lane

    if (tid == 0) slow_s = 0;
    for (int idx = tid; idx < 34 * 64; idx += 256)
        xpw_s[idx >> 6][idx & 63] = x_proj_w[idx];
    if (tid < DM) {
        float acc = 0.f;
        #pragma unroll
        for (int k = 0; k < 16; k++) acc = fmaf(lin2_w[k], lin1_w[k * 32 + tid], acc);
        wm_s[tid] = acc;
    }
    if (tid == 0) {
        float c = lin2_b[0];
        #pragma unroll
        for (int k = 0; k < 16; k++) c = fmaf(lin2_w[k], lin1_b[k], c);
        c_sm = c;
    }
    __syncthreads();
    if (tid < DI) {
        float acc = 0.f;
        #pragma unroll
        for (int m = 0; m < 32; m++) acc = fmaf(wm_s[m], out_proj_w[m * 64 + tid], acc);
        v_sm[tid] = acc;
        // A structure check: A[d][n] == -(n+1) ? (true for this dataset; fallback otherwise)
        int bad = 0;
        #pragma unroll
        for (int n = 0; n < 16; n++) {
            float a = -__expf(A_log[tid * 16 + n]);
            a_s[tid][n] = a;
            if (fabsf(a + (float)(n + 1)) > 1e-4f * (float)(n + 1)) bad = 1;
        }
        if (bad) atomicOr(&slow_s, 1);
    }

    // per-thread constants (in_proj weights packed as f32x2 pairs -> registers)
    ull wxh[16], wz[16];
    {
        const ull* p  = (const ull*)(in_proj_w + d * DM);
        const ull* pz = (const ull*)(in_proj_w + (DI + d) * DM);
        #pragma unroll
        for (int q = 0; q < 16; q++) { wxh[q] = p[q]; wz[q] = pz[q]; }
    }
    const float4 cw = *(const float4*)(conv_w + d * 4);
    const float cb = conv_b[d];
    const float2 dtw = *(const float2*)(dt_proj_w + d * 2);
    const float dtb = dt_proj_b[d];
    const float dpv = Dp[d];

    const int bb = blockIdx.x * 4 + j;
    const float* xbase = g_xr + bb * (SEQ * DM);
    if (w == 0 && l < 8)
        *(float4*)&xin_s[0][j][l * 4] = *(const float4*)(xbase + l * 4);
    __syncthreads();
    const float vv = v_sm[d];
    const int slow = slow_s;

    ull h2[8];
    #pragma unroll
    for (int q = 0; q < 8; q++) h2[q] = 0ull;
    float xm1 = 0.f, xm2 = 0.f, xm3 = 0.f;   // conv history

    for (int t = 0; t < SEQ; t++) {
        const int buf = t & 1;

        // ---- phase A: in_proj (packed FMA2, register weights), conv, SiLU ----
        ull accx = 0ull, accz = 0ull;
        const ull* xp = (const ull*)xin_s[buf][j];
        #pragma unroll
        for (int q = 0; q < 16; q++) {
            ull xv = xp[q];
            FMA2(accx, wxh[q], xv, accx);
            FMA2(accz, wz[q], xv, accz);
        }
        float2 fx = unpack2(accx), fz = unpack2(accz);
        const float xh0 = fx.x + fx.y;
        const float z = fz.x + fz.y;
        float xc = cb;
        xc = fmaf(cw.x, xm3, xc);
        xc = fmaf(cw.y, xm2, xc);
        xc = fmaf(cw.z, xm1, xc);
        xc = fmaf(cw.w, xh0, xc);
        xm3 = xm2; xm2 = xm1; xm1 = xh0;
        const float xt = __fdividef(xc, 1.f + __expf(-xc));
        xt_s[buf][j][d] = xt;

        // prefetch next input slab (warp-even, one 128B line)
        if (w == 0 && l < 8 && t + 1 < SEQ)
            *(float4*)&xin_s[buf ^ 1][j][l * 4] =
                *(const float4*)(xbase + (t + 1) * DM + l * 4);

        asm volatile("bar.sync %0, 64;" :: "r"(j + 1) : "memory");

        // ---- phase B: x_proj — lane l computes row l+2 (B/C), dt via butterfly ----
        {
            const ull* wr  = (const ull*)xpw_s[l + 2];
            const ull* xtp = (const ull*)xt_s[buf][j];
            ull acc = 0ull;
            #pragma unroll
            for (int q = 0; q < 32; q++) FMA2(acc, wr[q], xtp[q], acc);
            float2 a2 = unpack2(acc);
            dbc_s[j][w][l] = a2.x + a2.y;
        }
        const float2 xtl = *(const float2*)&xt_s[buf][j][2 * l];
        const float2 w0 = *(const float2*)&xpw_s[0][2 * l];
        const float2 w1 = *(const float2*)&xpw_s[1][2 * l];
        float u0 = fmaf(w0.y, xtl.y, w0.x * xtl.x);
        float u1 = fmaf(w1.y, xtl.y, w1.x * xtl.x);
        #pragma unroll
        for (int off = 16; off; off >>= 1) {
            u0 += __shfl_xor_sync(0xffffffffu, u0, off);
            u1 += __shfl_xor_sync(0xffffffffu, u1, off);
        }
        __syncwarp();

        // ---- phase C: delta, scan (packed, power-chain dA), gate, folded head ----
        const float dpre = fmaf(dtw.x, u0, fmaf(dtw.y, u1, dtb));
        const float delta = dpre > 15.f ? dpre : __logf(1.f + __expf(dpre));
        const float du = delta * xt;
        const ull du2 = pack2(du, du);
        ull y2 = 0ull;
        const float* db = dbc_s[j][w];
        if (!slow) {
            const float r = __expf(-delta);
            const float rr = r * r;
            ull cur = pack2(r, rr);            // (r^1, r^2)
            const ull rrd = pack2(rr, rr);
            #pragma unroll
            for (int q = 0; q < 8; q++) {
                ull bp = *(const ull*)&db[2 * q];
                ull cp = *(const ull*)&db[16 + 2 * q];
                ull tmp;
                MUL2(tmp, bp, du2);
                FMA2(h2[q], cur, h2[q], tmp);
                FMA2(y2, h2[q], cp, y2);
                if (q < 7) MUL2(cur, cur, rrd);
            }
        } else {
            #pragma unroll
            for (int q = 0; q < 8; q++) {
                float2 ap = *(const float2*)&a_s[d][2 * q];
                ull dA = pack2(__expf(delta * ap.x), __expf(delta * ap.y));
                ull bp = *(const ull*)&db[2 * q];
                ull cp = *(const ull*)&db[16 + 2 * q];
                ull tmp;
                MUL2(tmp, bp, du2);
                FMA2(h2[q], dA, h2[q], tmp);
                FMA2(y2, h2[q], cp, y2);
            }
        }
        float2 yp = unpack2(y2);
        float y = yp.x + yp.y;
        y = fmaf(xt, dpv, y);
        y *= __fdividef(z, 1.f + __expf(-z));

        float acc = y * vv;
        #pragma unroll
        for (int off = 16; off; off >>= 1) acc += __shfl_xor_sync(0xffffffffu, acc, off);
        if (l == 0) part_s[j][t][w] = acc;
        __syncwarp();
    }

    __syncthreads();
    {
        const int tt = tid >> 2;
        const int jj = tid & 3;
        const float val = part_s[jj][tt][0] + part_s[jj][tt][1] + c_sm;
        const int obb = blockIdx.x * 4 + jj;
        out[(obb >> 10) * (SEQ * HW) + tt * HW + (obb & (HW - 1))] = val;
    }
}

extern "C" void kernel_launch(void* const* d_in, const int* in_sizes, int n_in,
                              void* d_out, int out_size) {
    const float* x         = (const float*)d_in[0];
    const float* in_proj_w = (const float*)d_in[1];
    const float* conv_w    = (const float*)d_in[2];
    const float* conv_b    = (const float*)d_in[3];
    const float* x_proj_w  = (const float*)d_in[4];
    const float* dt_proj_w = (const float*)d_in[5];
    const float* dt_proj_b = (const float*)d_in[6];
    const float* A_log     = (const float*)d_in[7];
    const float* Dp        = (const float*)d_in[8];
    const float* out_proj_w= (const float*)d_in[9];
    const float* lin1_w    = (const float*)d_in[10];
    const float* lin1_b    = (const float*)d_in[11];
    const float* lin2_w    = (const float*)d_in[12];
    const float* lin2_b    = (const float*)d_in[13];
    float* out = (float*)d_out;

    transpose_kernel<<<2048, 256>>>(x);
    mamba_main<<<512, 256>>>(in_proj_w, conv_w, conv_b, x_proj_w,
                             dt_proj_w, dt_proj_b, A_log, Dp, out_proj_w,
                             lin1_w, lin1_b, lin2_w, lin2_b, out);
}

// round 5
// speedup vs baseline: 1.5093x; 1.5093x over previous
#include <cuda_runtime.h>
#include <cstdint>

typedef unsigned long long ull;

#define SEQ 64
#define DM 32
#define DI 64
#define HW 1024
#define TT 8

#define FMA2(d, a, b, c) \
    asm("fma.rn.f32x2 %0, %1, %2, %3;" : "=l"(d) : "l"(a), "l"(b), "l"(c))
#define MUL2(d, a, b) \
    asm("mul.rn.f32x2 %0, %1, %2;" : "=l"(d) : "l"(a), "l"(b))
__device__ __forceinline__ ull pack2(float lo, float hi) {
    ull r; asm("mov.b64 %0, {%1, %2};" : "=l"(r) : "f"(lo), "f"(hi)); return r;
}
__device__ __forceinline__ float2 unpack2(ull v) {
    float2 f; asm("mov.b64 {%0, %1}, %2;" : "=f"(f.x), "=f"(f.y) : "l"(v)); return f;
}
__device__ __forceinline__ ull lds64v(uint32_t a) {
    ull v; asm volatile("ld.shared.b64 %0, [%1];" : "=l"(v) : "r"(a)); return v;
}

__device__ float g_xr[2 * HW * SEQ * DM];

__global__ __launch_bounds__(256) void transpose_kernel(const float* __restrict__ x) {
    __shared__ float tile[DM][65];
    const int bi = blockIdx.x;
    const int c  = bi & 15;
    const int t  = (bi >> 4) & 63;
    const int b  = bi >> 10;
    const float* src = x + ((b * SEQ + t) * DM) * HW + c * 64;
    const int tid = threadIdx.x;
    #pragma unroll
    for (int i = 0; i < 8; i++) {
        int idx = tid + i * 256;
        tile[idx >> 6][idx & 63] = src[(idx >> 6) * HW + (idx & 63)];
    }
    __syncthreads();
    #pragma unroll
    for (int i = 0; i < 8; i++) {
        int idx = tid + i * 256;
        int hw = idx >> 5, m = idx & 31;
        g_xr[(b * HW + c * 64 + hw) * (SEQ * DM) + t * DM + m] = tile[m][hw];
    }
}

__global__ __launch_bounds__(256, 2) void mamba_main(
    const float* __restrict__ in_proj_w, const float* __restrict__ conv_w,
    const float* __restrict__ conv_b, const float* __restrict__ x_proj_w,
    const float* __restrict__ dt_proj_w, const float* __restrict__ dt_proj_b,
    const float* __restrict__ A_log, const float* __restrict__ Dp,
    const float* __restrict__ out_proj_w, const float* __restrict__ lin1_w,
    const float* __restrict__ lin1_b, const float* __restrict__ lin2_w,
    const float* __restrict__ lin2_b, float* __restrict__ out)
{
    __shared__ ull  winp_u[16][128];        // [q][r]: in_proj pairs; r<64 xh, r>=64 z
    __shared__ ull  xpw_u[16][64];          // [q][i]: B/C half-row pairs, i = 32w + l
    __shared__ ull  wdt_u[64];              // dt rows 0/1 pairs
    __shared__ float xin_s[2][4][TT][DM];   // double-buffered input tiles
    __shared__ float xt_s[4][TT][68];       // half0 @ [0..31], half1 @ [34..65]
    __shared__ float dbc_s[4][TT][36];      // [0:16)=B, [16:32)=C, [32]=u0, [33]=u1
    __shared__ float part_s[4][SEQ][2];
    __shared__ float wm_s[DM];
    __shared__ float v_s[DI];
    __shared__ float a_s[DI][18];
    __shared__ float c_s;
    __shared__ int slow_s;

    const int tid = threadIdx.x;
    const int j = tid >> 6;
    const int d = tid & 63;
    const int w = (tid >> 5) & 1;
    const int l = tid & 31;

    if (tid == 0) slow_s = 0;
    for (int idx = tid; idx < 2048; idx += 256) {
        int q = idx >> 7, r = idx & 127;
        float2 p = *(const float2*)&in_proj_w[r * DM + 2 * q];
        winp_u[q][r] = pack2(p.x, p.y);
    }
    for (int idx = tid; idx < 1024; idx += 256) {
        int q = idx >> 6, i = idx & 63;
        int wi = i >> 5, li = i & 31;
        int row = 2 + 16 * wi + (li >> 1), half = li & 1;
        float2 p = *(const float2*)&x_proj_w[row * DI + 32 * half + 2 * q];
        xpw_u[q][i] = pack2(p.x, p.y);
    }
    if (tid < 64) {
        int wi = tid >> 5, li = tid & 31;
        float2 p = *(const float2*)&x_proj_w[wi * DI + 2 * li];
        wdt_u[tid] = pack2(p.x, p.y);
    }
    if (tid < DM) {
        float acc = 0.f;
        #pragma unroll
        for (int k = 0; k < 16; k++) acc = fmaf(lin2_w[k], lin1_w[k * 32 + tid], acc);
        wm_s[tid] = acc;
    }
    if (tid == 0) {
        float c = lin2_b[0];
        #pragma unroll
        for (int k = 0; k < 16; k++) c = fmaf(lin2_w[k], lin1_b[k], c);
        c_s = c;
    }
    __syncthreads();
    if (tid < DI) {
        float acc = 0.f;
        #pragma unroll
        for (int m = 0; m < 32; m++) acc = fmaf(wm_s[m], out_proj_w[m * 64 + tid], acc);
        v_s[tid] = acc;
        int bad = 0;
        #pragma unroll
        for (int n = 0; n < 16; n++) {
            float a = -__expf(A_log[tid * 16 + n]);
            a_s[tid][n] = a;
            if (fabsf(a + (float)(n + 1)) > 1e-4f * (float)(n + 1)) bad = 1;
        }
        if (bad) atomicOr(&slow_s, 1);
    }

    const float4 cw = *(const float4*)(conv_w + d * 4);
    const float cb = conv_b[d];
    const float2 dtw = *(const float2*)(dt_proj_w + d * 2);
    const float dtb = dt_proj_b[d];
    const float dpv = Dp[d];

    const int bb = blockIdx.x * 4 + j;
    const float* xbase = g_xr + bb * (SEQ * DM);
    {
        float4 v4 = *(const float4*)(xbase + d * 4);
        *(float4*)&xin_s[0][j][d >> 3][(d & 7) * 4] = v4;
    }
    __syncthreads();
    const float vv = v_s[d];
    const int slow = slow_s;

    const uint32_t winp_a = (uint32_t)__cvta_generic_to_shared(&winp_u[0][0]);
    const uint32_t xpw_a  = (uint32_t)__cvta_generic_to_shared(&xpw_u[0][0]);
    const uint32_t wdt_a  = (uint32_t)__cvta_generic_to_shared(&wdt_u[0]);

    const int xpos = (d < 32) ? d : d + 2;
    float z8[TT], xtr[TT];
    ull h2[8];
    #pragma unroll
    for (int q = 0; q < 8; q++) h2[q] = 0ull;
    float xm1 = 0.f, xm2 = 0.f, xm3 = 0.f;

    for (int tile = 0; tile < SEQ / TT; tile++) {
        const int buf = tile & 1;

        // phase A: in_proj + conv + silu (weights per-tile in regs)
        {
            ull wa[16], wz[16];
            #pragma unroll
            for (int q = 0; q < 16; q++) {
                wa[q] = lds64v(winp_a + (uint32_t)(q * 128 + d) * 8u);
                wz[q] = lds64v(winp_a + (uint32_t)(q * 128 + 64 + d) * 8u);
            }
            #pragma unroll
            for (int tt = 0; tt < TT; tt++) {
                ull ax = 0ull, az = 0ull;
                const ull* xp = (const ull*)xin_s[buf][j][tt];
                #pragma unroll
                for (int q = 0; q < 16; q++) {
                    ull xv = xp[q];
                    FMA2(ax, wa[q], xv, ax);
                    FMA2(az, wz[q], xv, az);
                }
                float2 fx = unpack2(ax), fz = unpack2(az);
                const float xh = fx.x + fx.y;
                z8[tt] = fz.x + fz.y;
                float xc = cb;
                xc = fmaf(cw.x, xm3, xc);
                xc = fmaf(cw.y, xm2, xc);
                xc = fmaf(cw.z, xm1, xc);
                xc = fmaf(cw.w, xh, xc);
                xm3 = xm2; xm2 = xm1; xm1 = xh;
                const float xt = __fdividef(xc, 1.f + __expf(-xc));
                xtr[tt] = xt;
                xt_s[j][tt][xpos] = xt;
            }
        }
        asm volatile("bar.sync %0, 64;" :: "r"(j + 1) : "memory");

        // phase B: x_proj half-rows + dt, input prefetch
        {
            const bool ld = (tile + 1 < SEQ / TT);
            float4 pf;
            if (ld) pf = *(const float4*)(xbase + (tile + 1) * (TT * DM) + d * 4);

            ull wB[16];
            const int i = 32 * w + l;
            #pragma unroll
            for (int q = 0; q < 16; q++)
                wB[q] = lds64v(xpw_a + (uint32_t)(q * 64 + i) * 8u);
            const ull wdt = lds64v(wdt_a + (uint32_t)i * 8u);
            const float2 wdv = unpack2(wdt);
            const int hbyte = (l & 1) ? 136 : 0;
            const int dtoff = (l < 16) ? 8 * l : 8 * l + 8;
            const int pos = 16 * w + (l >> 1);

            #pragma unroll
            for (int tt = 0; tt < TT; tt++) {
                const char* rowp = (const char*)&xt_s[j][tt][0];
                const ull* xp = (const ull*)(rowp + hbyte);
                ull acc = 0ull;
                #pragma unroll
                for (int q = 0; q < 16; q++) FMA2(acc, wB[q], xp[q], acc);
                float2 a2 = unpack2(acc);
                float partial = a2.x + a2.y;
                partial += __shfl_xor_sync(0xffffffffu, partial, 1);
                if (!(l & 1)) dbc_s[j][tt][pos] = partial;

                float2 xv = *(const float2*)(rowp + dtoff);
                float u = fmaf(wdv.y, xv.y, wdv.x * xv.x);
                #pragma unroll
                for (int off = 16; off; off >>= 1)
                    u += __shfl_xor_sync(0xffffffffu, u, off);
                if (l == 0) dbc_s[j][tt][32 + w] = u;
            }
            if (ld) *(float4*)&xin_s[buf ^ 1][j][d >> 3][(d & 7) * 4] = pf;
        }
        asm volatile("bar.sync %0, 64;" :: "r"(j + 1) : "memory");

        // phase C: delta, scan, gate, folded head
        #pragma unroll
        for (int tt = 0; tt < TT; tt++) {
            const float* db = dbc_s[j][tt];
            const float2 uu = *(const float2*)&db[32];
            const float dpre = fmaf(dtw.x, uu.x, fmaf(dtw.y, uu.y, dtb));
            const float delta = dpre > 15.f ? dpre : __logf(1.f + __expf(dpre));
            const float xt = xtr[tt];
            const float du = delta * xt;
            const ull du2 = pack2(du, du);
            ull y2 = 0ull;
            if (!slow) {
                const float r = __expf(-delta);
                const float rr = r * r;
                ull cur = pack2(r, rr);
                const ull rrd = pack2(rr, rr);
                #pragma unroll
                for (int q = 0; q < 8; q++) {
                    ull bp = *(const ull*)&db[2 * q];
                    ull cp = *(const ull*)&db[16 + 2 * q];
                    ull tmp;
                    MUL2(tmp, bp, du2);
                    FMA2(h2[q], cur, h2[q], tmp);
                    FMA2(y2, h2[q], cp, y2);
                    if (q < 7) MUL2(cur, cur, rrd);
                }
            } else {
                #pragma unroll
                for (int q = 0; q < 8; q++) {
                    float2 ap = *(const float2*)&a_s[d][2 * q];
                    ull dA = pack2(__expf(delta * ap.x), __expf(delta * ap.y));
                    ull bp = *(const ull*)&db[2 * q];
                    ull cp = *(const ull*)&db[16 + 2 * q];
                    ull tmp;
                    MUL2(tmp, bp, du2);
                    FMA2(h2[q], dA, h2[q], tmp);
                    FMA2(y2, h2[q], cp, y2);
                }
            }
            float2 yp = unpack2(y2);
            float y = yp.x + yp.y;
            y = fmaf(xt, dpv, y);
            const float z = z8[tt];
            y *= __fdividef(z, 1.f + __expf(-z));

            float acc = y * vv;
            #pragma unroll
            for (int off = 16; off; off >>= 1)
                acc += __shfl_xor_sync(0xffffffffu, acc, off);
            if (l == 0) part_s[j][tile * TT + tt][w] = acc;
        }
    }

    __syncthreads();
    {
        const int tt = tid >> 2;
        const int jj = tid & 3;
        const float val = part_s[jj][tt][0] + part_s[jj][tt][1] + c_s;
        const int obb = blockIdx.x * 4 + jj;
        out[(obb >> 10) * (SEQ * HW) + tt * HW + (obb & (HW - 1))] = val;
    }
}

extern "C" void kernel_launch(void* const* d_in, const int* in_sizes, int n_in,
                              void* d_out, int out_size) {
    const float* x         = (const float*)d_in[0];
    const float* in_proj_w = (const float*)d_in[1];
    const float* conv_w    = (const float*)d_in[2];
    const float* conv_b    = (const float*)d_in[3];
    const float* x_proj_w  = (const float*)d_in[4];
    const float* dt_proj_w = (const float*)d_in[5];
    const float* dt_proj_b = (const float*)d_in[6];
    const float* A_log     = (const float*)d_in[7];
    const float* Dp        = (const float*)d_in[8];
    const float* out_proj_w= (const float*)d_in[9];
    const float* lin1_w    = (const float*)d_in[10];
    const float* lin1_b    = (const float*)d_in[11];
    const float* lin2_w    = (const float*)d_in[12];
    const float* lin2_b    = (const float*)d_in[13];
    float* out = (float*)d_out;

    transpose_kernel<<<2048, 256>>>(x);
    mamba_main<<<512, 256>>>(in_proj_w, conv_w, conv_b, x_proj_w,
                             dt_proj_w, dt_proj_b, A_log, Dp, out_proj_w,
                             lin1_w, lin1_b, lin2_w, lin2_b, out);
}

// round 6
// speedup vs baseline: 1.5616x; 1.0347x over previous
#include <cuda_runtime.h>
#include <cstdint>

typedef unsigned long long ull;

#define SEQ 64
#define DM 32
#define DI 64
#define HW 1024
#define TT 8

#define FMA2(d, a, b, c) \
    asm("fma.rn.f32x2 %0, %1, %2, %3;" : "=l"(d) : "l"(a), "l"(b), "l"(c))
#define MUL2(d, a, b) \
    asm("mul.rn.f32x2 %0, %1, %2;" : "=l"(d) : "l"(a), "l"(b))
__device__ __forceinline__ ull pack2(float lo, float hi) {
    ull r; asm("mov.b64 %0, {%1, %2};" : "=l"(r) : "f"(lo), "f"(hi)); return r;
}
__device__ __forceinline__ float2 unpack2(ull v) {
    float2 f; asm("mov.b64 {%0, %1}, %2;" : "=f"(f.x), "=f"(f.y) : "l"(v)); return f;
}
// volatile LDS (keep per-tile weight fills inside the tile loop)
__device__ __forceinline__ ull lds64v(uint32_t a) {
    ull v; asm volatile("ld.shared.b64 %0, [%1];" : "=l"(v) : "r"(a)); return v;
}
__device__ __forceinline__ float4 lds128v(uint32_t a) {
    float4 v;
    asm volatile("ld.shared.v4.f32 {%0,%1,%2,%3}, [%4];"
                 : "=f"(v.x), "=f"(v.y), "=f"(v.z), "=f"(v.w) : "r"(a));
    return v;
}

__device__ float g_xr[2 * HW * SEQ * DM];

__global__ __launch_bounds__(256) void transpose_kernel(const float* __restrict__ x) {
    __shared__ float tile[DM][65];
    const int bi = blockIdx.x;
    const int c  = bi & 15;
    const int t  = (bi >> 4) & 63;
    const int b  = bi >> 10;
    const float* src = x + ((b * SEQ + t) * DM) * HW + c * 64;
    const int tid = threadIdx.x;
    #pragma unroll
    for (int i = 0; i < 8; i++) {
        int idx = tid + i * 256;
        tile[idx >> 6][idx & 63] = src[(idx >> 6) * HW + (idx & 63)];
    }
    __syncthreads();
    #pragma unroll
    for (int i = 0; i < 8; i++) {
        int idx = tid + i * 256;
        int hw = idx >> 5, m = idx & 31;
        g_xr[(b * HW + c * 64 + hw) * (SEQ * DM) + t * DM + m] = tile[m][hw];
    }
}

__global__ __launch_bounds__(256, 2) void mamba_main(
    const float* __restrict__ in_proj_w, const float* __restrict__ conv_w,
    const float* __restrict__ conv_b, const float* __restrict__ x_proj_w,
    const float* __restrict__ dt_proj_w, const float* __restrict__ dt_proj_b,
    const float* __restrict__ A_log, const float* __restrict__ Dp,
    const float* __restrict__ out_proj_w, const float* __restrict__ lin1_w,
    const float* __restrict__ lin1_b, const float* __restrict__ lin2_w,
    const float* __restrict__ lin2_b, float* __restrict__ out)
{
    __shared__ float4 winp4[8][128];        // [qq][r]: in_proj 4-wide; r<64 xh row r, r>=64 z
    __shared__ float4 xpw4[8][64];          // [qq][i]: B/C half-row 4-wide, i = 32w + l
    __shared__ ull    wdt_u[64];            // dt rows 0/1 pairs
    __shared__ float  xin_s[2][4][TT][DM];  // double-buffered input tiles (v4-readable)
    __shared__ float  xt_s[4][TT][72];      // half0 @ [0..31], half1 @ [36..67]
    __shared__ float  dbc_s[4][TT][40];     // [0:16)=B, [16:32)=C, [32]=u0, [33]=u1
    __shared__ float  part_s[4][SEQ][2];
    __shared__ float  wm_s[DM];
    __shared__ float  v_s[DI];
    __shared__ float  a_s[DI][18];
    __shared__ float  c_s;
    __shared__ int    slow_s;

    const int tid = threadIdx.x;
    const int j = tid >> 6;
    const int d = tid & 63;
    const int w = (tid >> 5) & 1;
    const int l = tid & 31;

    if (tid == 0) slow_s = 0;
    for (int idx = tid; idx < 1024; idx += 256) {
        int qq = idx >> 7, r = idx & 127;
        winp4[qq][r] = *(const float4*)&in_proj_w[r * DM + 4 * qq];
    }
    for (int idx = tid; idx < 512; idx += 256) {
        int qq = idx >> 6, i = idx & 63;
        int wi = i >> 5, li = i & 31;
        int row = 2 + 16 * wi + (li >> 1), half = li & 1;
        xpw4[qq][i] = *(const float4*)&x_proj_w[row * DI + 32 * half + 4 * qq];
    }
    if (tid < 64) {
        int wi = tid >> 5, li = tid & 31;
        float2 p = *(const float2*)&x_proj_w[wi * DI + 2 * li];
        wdt_u[tid] = pack2(p.x, p.y);
    }
    if (tid < DM) {
        float acc = 0.f;
        #pragma unroll
        for (int k = 0; k < 16; k++) acc = fmaf(lin2_w[k], lin1_w[k * 32 + tid], acc);
        wm_s[tid] = acc;
    }
    if (tid == 0) {
        float c = lin2_b[0];
        #pragma unroll
        for (int k = 0; k < 16; k++) c = fmaf(lin2_w[k], lin1_b[k], c);
        c_s = c;
    }
    __syncthreads();
    if (tid < DI) {
        float acc = 0.f;
        #pragma unroll
        for (int m = 0; m < 32; m++) acc = fmaf(wm_s[m], out_proj_w[m * 64 + tid], acc);
        v_s[tid] = acc;
        int bad = 0;
        #pragma unroll
        for (int n = 0; n < 16; n++) {
            float a = -__expf(A_log[tid * 16 + n]);
            a_s[tid][n] = a;
            if (fabsf(a + (float)(n + 1)) > 1e-4f * (float)(n + 1)) bad = 1;
        }
        if (bad) atomicOr(&slow_s, 1);
    }

    const float4 cw = *(const float4*)(conv_w + d * 4);
    const float cb = conv_b[d];
    const float2 dtw = *(const float2*)(dt_proj_w + d * 2);
    const float dtb = dt_proj_b[d];
    const float dpv = Dp[d];

    const int bb = blockIdx.x * 4 + j;
    const float* xbase = g_xr + bb * (SEQ * DM);
    {
        float4 v4 = *(const float4*)(xbase + d * 4);
        *(float4*)&xin_s[0][j][d >> 3][(d & 7) * 4] = v4;
    }
    __syncthreads();
    const float vv = v_s[d];
    const int slow = slow_s;

    const uint32_t winp_a = (uint32_t)__cvta_generic_to_shared(&winp4[0][0]);
    const uint32_t xpw_a  = (uint32_t)__cvta_generic_to_shared(&xpw4[0][0]);
    const uint32_t wdt_a  = (uint32_t)__cvta_generic_to_shared(&wdt_u[0]);

    const int xpos = (d < 32) ? d : d + 4;   // half1 starts at 36
    float z8[TT], xtr[TT];
    ull h2[8];
    #pragma unroll
    for (int q = 0; q < 8; q++) h2[q] = 0ull;
    float xm1 = 0.f, xm2 = 0.f, xm3 = 0.f;

    for (int tile = 0; tile < SEQ / TT; tile++) {
        const int buf = tile & 1;

        // ---- phase A: in_proj + conv + silu ----
        {
            ull wa[16], wz[16];
            #pragma unroll
            for (int qq = 0; qq < 8; qq++) {
                float4 a4 = lds128v(winp_a + (uint32_t)(qq * 128 + d) * 16u);
                wa[2 * qq] = pack2(a4.x, a4.y);
                wa[2 * qq + 1] = pack2(a4.z, a4.w);
                float4 z4 = lds128v(winp_a + (uint32_t)(qq * 128 + 64 + d) * 16u);
                wz[2 * qq] = pack2(z4.x, z4.y);
                wz[2 * qq + 1] = pack2(z4.z, z4.w);
            }
            #pragma unroll
            for (int tt = 0; tt < TT; tt++) {
                ull ax = 0ull, az = 0ull;
                const float4* xp4 = (const float4*)xin_s[buf][j][tt];
                #pragma unroll
                for (int qq = 0; qq < 8; qq++) {
                    float4 xv4 = xp4[qq];
                    ull lo = pack2(xv4.x, xv4.y);
                    ull hi = pack2(xv4.z, xv4.w);
                    FMA2(ax, wa[2 * qq], lo, ax);
                    FMA2(az, wz[2 * qq], lo, az);
                    FMA2(ax, wa[2 * qq + 1], hi, ax);
                    FMA2(az, wz[2 * qq + 1], hi, az);
                }
                float2 fx = unpack2(ax), fz = unpack2(az);
                const float xh = fx.x + fx.y;
                z8[tt] = fz.x + fz.y;
                float xc = cb;
                xc = fmaf(cw.x, xm3, xc);
                xc = fmaf(cw.y, xm2, xc);
                xc = fmaf(cw.z, xm1, xc);
                xc = fmaf(cw.w, xh, xc);
                xm3 = xm2; xm2 = xm1; xm1 = xh;
                const float xt = __fdividef(xc, 1.f + __expf(-xc));
                xtr[tt] = xt;
                xt_s[j][tt][xpos] = xt;
            }
        }
        asm volatile("bar.sync %0, 64;" :: "r"(j + 1) : "memory");

        // ---- phase B: x_proj half-rows + dt, input prefetch ----
        {
            const bool ld = (tile + 1 < SEQ / TT);
            float4 pf;
            if (ld) pf = *(const float4*)(xbase + (tile + 1) * (TT * DM) + d * 4);

            ull wB[16];
            const int i = 32 * w + l;
            #pragma unroll
            for (int qq = 0; qq < 8; qq++) {
                float4 b4 = lds128v(xpw_a + (uint32_t)(qq * 64 + i) * 16u);
                wB[2 * qq] = pack2(b4.x, b4.y);
                wB[2 * qq + 1] = pack2(b4.z, b4.w);
            }
            const ull wdt = lds64v(wdt_a + (uint32_t)i * 8u);
            const float2 wdv = unpack2(wdt);
            const int hbyte = (l & 1) ? 144 : 0;                 // half1 @ float 36
            const int dtoff = (l < 16) ? 8 * l : 8 * l + 16;     // own-channel pair
            const int pos = 16 * w + (l >> 1);

            #pragma unroll
            for (int tt = 0; tt < TT; tt++) {
                const char* rowp = (const char*)&xt_s[j][tt][0];
                const float4* xp = (const float4*)(rowp + hbyte);
                ull acc = 0ull;
                #pragma unroll
                for (int qq = 0; qq < 8; qq++) {
                    float4 xv4 = xp[qq];
                    ull lo = pack2(xv4.x, xv4.y);
                    ull hi = pack2(xv4.z, xv4.w);
                    FMA2(acc, wB[2 * qq], lo, acc);
                    FMA2(acc, wB[2 * qq + 1], hi, acc);
                }
                float2 a2 = unpack2(acc);
                float partial = a2.x + a2.y;
                partial += __shfl_xor_sync(0xffffffffu, partial, 1);
                if (!(l & 1)) dbc_s[j][tt][pos] = partial;

                float2 xv = *(const float2*)(rowp + dtoff);
                float u = fmaf(wdv.y, xv.y, wdv.x * xv.x);
                #pragma unroll
                for (int off = 16; off; off >>= 1)
                    u += __shfl_xor_sync(0xffffffffu, u, off);
                if (l == 0) dbc_s[j][tt][32 + w] = u;
            }
            if (ld) *(float4*)&xin_s[buf ^ 1][j][d >> 3][(d & 7) * 4] = pf;
        }
        asm volatile("bar.sync %0, 64;" :: "r"(j + 1) : "memory");

        // ---- phase C1: per-step scalars (independent across steps) ----
        float du_s[TT], r_s[TT];
        #pragma unroll
        for (int tt = 0; tt < TT; tt++) {
            const float2 uu = *(const float2*)&dbc_s[j][tt][32];
            const float dpre = fmaf(dtw.x, uu.x, fmaf(dtw.y, uu.y, dtb));
            const float delta = dpre > 15.f ? dpre : __logf(1.f + __expf(dpre));
            du_s[tt] = delta * xtr[tt];
            r_s[tt] = __expf(-delta);
        }
        // ---- phase C2: scan chain + gate + folded head ----
        #pragma unroll
        for (int tt = 0; tt < TT; tt++) {
            const float* db = dbc_s[j][tt];
            const ull du2 = pack2(du_s[tt], du_s[tt]);
            ull y2a = 0ull, y2b = 0ull;
            if (!slow) {
                const float r = r_s[tt];
                const float rr = r * r;
                ull cur = pack2(r, rr);
                const ull rrd = pack2(rr, rr);
                #pragma unroll
                for (int qq = 0; qq < 4; qq++) {
                    float4 b4 = *(const float4*)&db[4 * qq];
                    float4 c4 = *(const float4*)&db[16 + 4 * qq];
                    ull bp = pack2(b4.x, b4.y), cp = pack2(c4.x, c4.y);
                    ull tmp;
                    MUL2(tmp, bp, du2);
                    FMA2(h2[2 * qq], cur, h2[2 * qq], tmp);
                    FMA2(y2a, h2[2 * qq], cp, y2a);
                    MUL2(cur, cur, rrd);
                    bp = pack2(b4.z, b4.w); cp = pack2(c4.z, c4.w);
                    MUL2(tmp, bp, du2);
                    FMA2(h2[2 * qq + 1], cur, h2[2 * qq + 1], tmp);
                    FMA2(y2b, h2[2 * qq + 1], cp, y2b);
                    if (qq < 3) MUL2(cur, cur, rrd);
                }
            } else {
                const float delta = du_s[tt] == 0.f ? 0.f : du_s[tt] / xtr[tt];
                #pragma unroll
                for (int qq = 0; qq < 4; qq++) {
                    float4 b4 = *(const float4*)&db[4 * qq];
                    float4 c4 = *(const float4*)&db[16 + 4 * qq];
                    float4 ap = *(const float4*)&a_s[d][4 * qq];
                    ull dA = pack2(__expf(delta * ap.x), __expf(delta * ap.y));
                    ull bp = pack2(b4.x, b4.y), cp = pack2(c4.x, c4.y);
                    ull tmp;
                    MUL2(tmp, bp, du2);
                    FMA2(h2[2 * qq], dA, h2[2 * qq], tmp);
                    FMA2(y2a, h2[2 * qq], cp, y2a);
                    dA = pack2(__expf(delta * ap.z), __expf(delta * ap.w));
                    bp = pack2(b4.z, b4.w); cp = pack2(c4.z, c4.w);
                    MUL2(tmp, bp, du2);
                    FMA2(h2[2 * qq + 1], dA, h2[2 * qq + 1], tmp);
                    FMA2(y2b, h2[2 * qq + 1], cp, y2b);
                }
            }
            float2 ya = unpack2(y2a), yb = unpack2(y2b);
            float y = (ya.x + ya.y) + (yb.x + yb.y);
            y = fmaf(xtr[tt], dpv, y);
            const float z = z8[tt];
            y *= __fdividef(z, 1.f + __expf(-z));

            float acc = y * vv;
            #pragma unroll
            for (int off = 16; off; off >>= 1)
                acc += __shfl_xor_sync(0xffffffffu, acc, off);
            if (l == 0) part_s[j][tile * TT + tt][w] = acc;
        }
    }

    __syncthreads();
    {
        const int tt = tid >> 2;
        const int jj = tid & 3;
        const float val = part_s[jj][tt][0] + part_s[jj][tt][1] + c_s;
        const int obb = blockIdx.x * 4 + jj;
        out[(obb >> 10) * (SEQ * HW) + tt * HW + (obb & (HW - 1))] = val;
    }
}

extern "C" void kernel_launch(void* const* d_in, const int* in_sizes, int n_in,
                              void* d_out, int out_size) {
    const float* x         = (const float*)d_in[0];
    const float* in_proj_w = (const float*)d_in[1];
    const float* conv_w    = (const float*)d_in[2];
    const float* conv_b    = (const float*)d_in[3];
    const float* x_proj_w  = (const float*)d_in[4];
    const float* dt_proj_w = (const float*)d_in[5];
    const float* dt_proj_b = (const float*)d_in[6];
    const float* A_log     = (const float*)d_in[7];
    const float* Dp        = (const float*)d_in[8];
    const float* out_proj_w= (const float*)d_in[9];
    const float* lin1_w    = (const float*)d_in[10];
    const float* lin1_b    = (const float*)d_in[11];
    const float* lin2_w    = (const float*)d_in[12];
    const float* lin2_b    = (const float*)d_in[13];
    float* out = (float*)d_out;

    transpose_kernel<<<2048, 256>>>(x);
    mamba_main<<<512, 256>>>(in_proj_w, conv_w, conv_b, x_proj_w,
                             dt_proj_w, dt_proj_b, A_log, Dp, out_proj_w,
                             lin1_w, lin1_b, lin2_w, lin2_b, out);
}